// round 4
// baseline (speedup 1.0000x reference)
#include <cuda_runtime.h>
#include <cstdint>

// Problem constants
#define T 4
#define E 250000
#define D 128
#define B 4096
#define L 50

// 128-bit gather with L2 evict_last via cache-policy register (legal at v4 width).
__device__ __forceinline__ float4 ldg4_policy(const float4* p, uint64_t pol) {
    float4 v;
    asm("ld.global.nc.L2::cache_hint.v4.f32 {%0,%1,%2,%3}, [%4], %5;"
        : "=f"(v.x), "=f"(v.y), "=f"(v.z), "=f"(v.w)
        : "l"(p), "l"(pol));
    return v;
}

// Streaming 128-bit store (write-once output; don't pollute L2).
__device__ __forceinline__ void stg_cs4(float4* p, float4 v) {
    asm volatile("st.global.cs.v4.f32 [%0], {%1,%2,%3,%4};"
                 :: "l"(p), "f"(v.x), "f"(v.y), "f"(v.z), "f"(v.w));
}

// One warp per bag (t, b). Lane ln owns float4 at column ln*4.
__global__ __launch_bounds__(256)
void embbag_kernel(const float4* __restrict__ weights4,
                   const int*    __restrict__ indices,
                   float4*       __restrict__ out4) {
    const int warp_global = (blockIdx.x * blockDim.x + threadIdx.x) >> 5;
    const int lane = threadIdx.x & 31;
    if (warp_global >= T * B) return;

    uint64_t pol;
    asm("createpolicy.fractional.L2::evict_last.b64 %0, 1.0;" : "=l"(pol));

    const int t = warp_global >> 12;        // / B (4096)
    const int b = warp_global & (B - 1);

    const int* __restrict__ idx = indices + ((size_t)t * B + b) * L;

    // Preload all 50 indices: 2 coalesced loads, distribute via shfl.
    const int ia = __ldg(idx + lane);                               // idx[0..31]
    const int ib = (lane < (L - 32)) ? __ldg(idx + 32 + lane) : 0;  // idx[32..49]

    const float4* __restrict__ wt = weights4 + (size_t)t * E * (D / 4);

    float4 a0 = make_float4(0.f, 0.f, 0.f, 0.f);
    float4 a1 = make_float4(0.f, 0.f, 0.f, 0.f);

    // 10 groups of 5 independent LDG.128 (indices already in registers,
    // nothing but the gather itself in the dependency chain).
    #pragma unroll
    for (int l = 0; l < L; l += 5) {
        const float4* p[5];
        #pragma unroll
        for (int k = 0; k < 5; k++) {
            const int ll = l + k;           // warp-uniform selector
            const int j = (ll < 32) ? __shfl_sync(0xffffffffu, ia, ll)
                                    : __shfl_sync(0xffffffffu, ib, ll - 32);
            p[k] = wt + (size_t)j * (D / 4) + lane;
        }
        float4 r0 = ldg4_policy(p[0], pol);
        float4 r1 = ldg4_policy(p[1], pol);
        float4 r2 = ldg4_policy(p[2], pol);
        float4 r3 = ldg4_policy(p[3], pol);
        float4 r4 = ldg4_policy(p[4], pol);

        a0.x += r0.x + r2.x + r4.x;  a1.x += r1.x + r3.x;
        a0.y += r0.y + r2.y + r4.y;  a1.y += r1.y + r3.y;
        a0.z += r0.z + r2.z + r4.z;  a1.z += r1.z + r3.z;
        a0.w += r0.w + r2.w + r4.w;  a1.w += r1.w + r3.w;
    }

    const float4 acc = make_float4(a0.x + a1.x, a0.y + a1.y,
                                   a0.z + a1.z, a0.w + a1.w);

    // out[b][t*D + lane*4 .. +3], coalesced 512B per warp
    stg_cs4(out4 + ((size_t)b * T + t) * (D / 4) + lane, acc);
}

extern "C" void kernel_launch(void* const* d_in, const int* in_sizes, int n_in,
                              void* d_out, int out_size) {
    const float4* weights4 = (const float4*)d_in[0];  // [T, E, D] fp32
    const int*    indices  = (const int*)d_in[1];     // [T, B, L] int32
    float4*       out4     = (float4*)d_out;          // [B, T*D] fp32

    const int total_warps = T * B;                    // 16384 bags
    const int threads = 256;                          // 8 warps / CTA
    const int blocks = (total_warps * 32) / threads;  // 2048

    embbag_kernel<<<blocks, threads>>>(weights4, indices, out4);
}